// round 13
// baseline (speedup 1.0000x reference)
#include <cuda_runtime.h>
#include <cuda_fp16.h>
#include <cstdint>
#include <cstring>

// ---------------------------------------------------------------------------
// Problem constants
// ---------------------------------------------------------------------------
#define SEQ   2048
#define DM    4096
#define NH    32
#define NKV   8
#define HD    128
#define KVD   (NKV * HD)   // 1024

typedef __half h16;

// ---------------------------------------------------------------------------
// Device-global scratch (allocation-free rule)
// ---------------------------------------------------------------------------
__device__ float g_xq[SEQ * DM];
__device__ float g_xk[SEQ * KVD];
__device__ float g_xv[SEQ * KVD];

__device__ __align__(16) h16 g_xh [SEQ * DM],  g_xl [SEQ * DM];  // x split
__device__ __align__(16) h16 g_qh [SEQ * DM],  g_ql [SEQ * DM];  // q split
__device__ __align__(16) h16 g_kh [SEQ * KVD], g_kl [SEQ * KVD]; // k split
__device__ __align__(16) h16 g_vth[NKV * HD * SEQ];              // V^T plain
__device__ __align__(16) h16 g_ath[SEQ * DM];                    // attention out

// exact fp16 nibble planes (weight = nib * group_scale)
__device__ __align__(16) h16 g_nibq[DM * DM];
__device__ __align__(16) h16 g_nibk[KVD * DM];
__device__ __align__(16) h16 g_nibv[KVD * DM];
__device__ __align__(16) h16 g_nibo[DM * DM];

__device__ int g_mode;

// ---------------------------------------------------------------------------
// PTX helpers (base sm_103 ISA: cp.async / ldmatrix / mma.sync)
// ---------------------------------------------------------------------------
__device__ __forceinline__ uint32_t smem_u32(const void* p) {
    uint32_t a;
    asm("{ .reg .u64 t; cvta.to.shared.u64 t, %1; cvt.u32.u64 %0, t; }" : "=r"(a) : "l"(p));
    return a;
}
__device__ __forceinline__ void cp16(uint32_t dst, const void* src) {
    asm volatile("cp.async.cg.shared.global [%0], [%1], 16;" :: "r"(dst), "l"(src) : "memory");
}
__device__ __forceinline__ void cp4(uint32_t dst, const void* src) {
    asm volatile("cp.async.ca.shared.global [%0], [%1], 4;" :: "r"(dst), "l"(src) : "memory");
}
__device__ __forceinline__ void cp_commit() {
    asm volatile("cp.async.commit_group;" ::: "memory");
}
template <int N>
__device__ __forceinline__ void cp_wait() {
    asm volatile("cp.async.wait_group %0;" :: "n"(N) : "memory");
}
__device__ __forceinline__ void ldm_x4(uint32_t* r, uint32_t addr) {
    asm volatile("ldmatrix.sync.aligned.m8n8.x4.shared.b16 {%0,%1,%2,%3}, [%4];"
                 : "=r"(r[0]), "=r"(r[1]), "=r"(r[2]), "=r"(r[3]) : "r"(addr));
}
__device__ __forceinline__ void mma_f32(float* d, const uint32_t* a,
                                        uint32_t b0, uint32_t b1) {
    asm volatile(
        "mma.sync.aligned.m16n8k16.row.col.f32.f16.f16.f32 "
        "{%0,%1,%2,%3}, {%4,%5,%6,%7}, {%8,%9}, {%0,%1,%2,%3};"
        : "+f"(d[0]), "+f"(d[1]), "+f"(d[2]), "+f"(d[3])
        : "r"(a[0]), "r"(a[1]), "r"(a[2]), "r"(a[3]), "r"(b0), "r"(b1));
}
__device__ __forceinline__ void mma_f16(uint32_t* d, const uint32_t* a,
                                        uint32_t b0, uint32_t b1) {
    asm volatile(
        "mma.sync.aligned.m16n8k16.row.col.f16.f16.f16.f16 "
        "{%0,%1}, {%2,%3,%4,%5}, {%6,%7}, {%0,%1};"
        : "+r"(d[0]), "+r"(d[1])
        : "r"(a[0]), "r"(a[1]), "r"(a[2]), "r"(a[3]), "r"(b0), "r"(b1));
}

// Pack two floats into one uint32 holding an fp16 pair (BOTH halves).
__device__ __forceinline__ uint32_t pack_h2(float a, float b) {
    __half2 t = __floats2half2_rn(a, b);
    uint32_t r;
    memcpy(&r, &t, 4);
    return r;
}

// Permuted conflict-free smem layouts: atom = 8 rows x 16B, 128B blocks.
__device__ __forceinline__ uint32_t off8(int row, int kc) {   // 64-wide fp16 tile
    return (uint32_t)((((row >> 3) * 8 + kc) << 7) + ((row & 7) << 4));
}
__device__ __forceinline__ uint32_t off16(int row, int kc) {  // 128-wide fp16 tile
    return (uint32_t)((((row >> 3) * 16 + kc) << 7) + ((row & 7) << 4));
}

// ---------------------------------------------------------------------------
// Probe (dtype-robust weight ingestion)
// ---------------------------------------------------------------------------
__global__ void probe_mode(const int* __restrict__ w)
{
    if (threadIdx.x == 0 && blockIdx.x == 0) {
        int ok = 0;
        for (int i = 0; i < 256; i++) {
            const int v = w[i];
            if (v >= -128 && v <= 127) ok++;
        }
        g_mode = (ok >= 250) ? 1 : 0;
    }
}

// Unpack Q4_0 nibbles directly from raw input (mode-aware) to fp16 planes.
__global__ __launch_bounds__(256) void unpack_nib_h(
    const void* __restrict__ in, h16* __restrict__ nib, long n)
{
    const int mode = g_mode;
    const long stride = (long)gridDim.x * blockDim.x;
    for (long f = (long)blockIdx.x * blockDim.x + threadIdx.x; f < n; f += stride) {
        const int  q = (int)(f & 127);
        const long b = (f >> 7) * 64 + (q & 63);
        const int8_t raw = mode ? (int8_t)((const int*)in)[b]
                                : ((const int8_t*)in)[b];
        const int v = (q < 64) ? (raw >> 4) : (((int8_t)(raw << 4)) >> 4);
        nib[f] = __float2half((float)v);
    }
}

// fp32 -> fp16 hi/lo split
__global__ __launch_bounds__(256) void split_f32(
    const float* __restrict__ src, h16* __restrict__ hi, h16* __restrict__ lo, long n)
{
    const long stride = (long)gridDim.x * blockDim.x;
    for (long i = (long)blockIdx.x * blockDim.x + threadIdx.x; i < n; i += stride) {
        const float v = src[i];
        const h16 h = __float2half(v);
        hi[i] = h;
        lo[i] = __float2half(v - __half2float(h));
    }
}

// ---------------------------------------------------------------------------
// RoPE (rotate-half) + optional scale + fp16 split.  x laid out [S, nh, HD].
// ---------------------------------------------------------------------------
__global__ __launch_bounds__(256) void rope_split(
    const float* __restrict__ x, const float* __restrict__ cosb,
    const float* __restrict__ sinb, h16* __restrict__ oh, h16* __restrict__ ol,
    int nheads, float scale)
{
    const long total = (long)SEQ * nheads * 64;
    long idx = (long)blockIdx.x * blockDim.x + threadIdx.x;
    if (idx >= total) return;
    const int d = (int)(idx & 63);
    const int h = (int)((idx >> 6) % nheads);
    const int s = (int)(idx / ((long)64 * nheads));
    const size_t base = (size_t)s * nheads * HD + h * HD + d;
    const float c  = cosb[s * 64 + d];
    const float sn = sinb[s * 64 + d];
    const float lo = x[base];
    const float hi = x[base + 64];
    const float r0 = (lo * c - hi * sn) * scale;
    const float r1 = (hi * c + lo * sn) * scale;
    h16 h0 = __float2half(r0);
    h16 h1 = __float2half(r1);
    oh[base]      = h0;
    ol[base]      = __float2half(r0 - __half2float(h0));
    oh[base + 64] = h1;
    ol[base + 64] = __float2half(r1 - __half2float(h1));
}

// ---------------------------------------------------------------------------
// Transpose V to plain fp16: vt[kv][d][s] = xv[s][kv*HD + d]
// ---------------------------------------------------------------------------
__global__ __launch_bounds__(256) void vtrans_h(
    const float* __restrict__ xv, h16* __restrict__ vt)
{
    const long total = (long)NKV * HD * SEQ;
    long idx = (long)blockIdx.x * blockDim.x + threadIdx.x;
    if (idx >= total) return;
    const int s  = (int)(idx % SEQ);
    const int d  = (int)((idx / SEQ) % HD);
    const int kv = (int)(idx / ((long)SEQ * HD));
    vt[idx] = __float2half(xv[(size_t)s * KVD + kv * HD + d]);
}

// ---------------------------------------------------------------------------
// Merged QKV projection GEMM.  CTA tile 64(M) x 128(N), BK=64, 512 threads,
// 16 warps 4x4 (warp tile 16x32), 3-stage cp.async.
// blockIdx.x selects region: [0,32) q, [32,40) k, [40,48) v.
// q/k use two activation terms (xh+xl, exact); v uses one (xh).
// Weight = fp16 nibble (exact) * fp32 group scale drained per BK=64 group.
// ---------------------------------------------------------------------------
#define QKV_STAGE 32768        // Ah 8K | Al 8K | nib 16K
#define QKV_SMEM  (3 * QKV_STAGE + 3 * 512)

__global__ __launch_bounds__(512, 1) void gemm_qkv(
    const h16* __restrict__ xh, const h16* __restrict__ xl,
    const h16* __restrict__ nq, const h16* __restrict__ nk,
    const h16* __restrict__ nv,
    const float* __restrict__ sq, const float* __restrict__ sk,
    const float* __restrict__ sv,
    float* __restrict__ xq, float* __restrict__ xk, float* __restrict__ xv)
{
    const int nx = blockIdx.x;
    const int m0 = blockIdx.y * 64;

    const h16* Nib;
    const float* Sc;
    float* C;
    int ldc, n0, two;
    if (nx < 32)      { Nib = nq; Sc = sq; C = xq; ldc = DM;  n0 = nx * 128;        two = 1; }
    else if (nx < 40) { Nib = nk; Sc = sk; C = xk; ldc = KVD; n0 = (nx - 32) * 128; two = 1; }
    else              { Nib = nv; Sc = sv; C = xv; ldc = KVD; n0 = (nx - 40) * 128; two = 0; }

    extern __shared__ char smem[];
    const uint32_t sb  = smem_u32(smem);
    const uint32_t ssc = sb + 3 * QKV_STAGE;
    const int tid  = threadIdx.x;
    const int wid  = tid >> 5;
    const int lane = tid & 31;

    const int NC = DM >> 6;          // 64 chunks
    const int wm = (wid & 3) * 16;
    const int wn = (wid >> 2) * 32;

    float accf[4][4];
#pragma unroll
    for (int j = 0; j < 4; j++)
#pragma unroll
        for (int v = 0; v < 4; v++) accf[j][v] = 0.0f;

    auto load_stage = [&](int c) {
        const int k0 = c << 6;
        const uint32_t st = sb + (uint32_t)(c % 3) * QKV_STAGE;
        {   // Ah: 64 rows x 8 chunks = 512 -> 1 per thread
            const int row = tid >> 3, kc = tid & 7;
            cp16(st + off8(row, kc), xh + (size_t)(m0 + row) * DM + k0 + kc * 8);
            if (two)
                cp16(st + 8192 + off8(row, kc), xl + (size_t)(m0 + row) * DM + k0 + kc * 8);
        }
#pragma unroll
        for (int it = 0; it < 2; it++) {   // nib: 128 rows x 8 chunks = 1024
            const int i = tid + it * 512;
            const int row = i >> 3, kc = i & 7;
            cp16(st + 16384 + off8(row, kc), Nib + (size_t)(n0 + row) * DM + k0 + kc * 8);
        }
        if (tid < 128)
            cp4(ssc + (uint32_t)(c % 3) * 512 + tid * 4,
                Sc + (size_t)(n0 + tid) * (DM >> 6) + c);
        cp_commit();
    };

    load_stage(0);
    load_stage(1);

    const int lrow16 = lane & 15;
    const int lhi    = lane >> 4;

    for (int c = 0; c < NC; c++) {
        if (c + 1 < NC) cp_wait<1>();
        else            cp_wait<0>();
        __syncthreads();

        const uint32_t st = sb + (uint32_t)(c % 3) * QKV_STAGE;
        const float* ss = (const float*)(smem + 3 * QKV_STAGE + (c % 3) * 512);

        float accg[4][4];
#pragma unroll
        for (int j = 0; j < 4; j++)
#pragma unroll
            for (int v = 0; v < 4; v++) accg[j][v] = 0.0f;

#pragma unroll
        for (int kb = 0; kb < 4; kb++) {
            uint32_t afh[4], afl[4];
            const uint32_t aoff = off8(wm + lrow16, kb * 2 + lhi);
            ldm_x4(afh, st + aoff);
            if (two) ldm_x4(afl, st + 8192 + aoff);
#pragma unroll
            for (int g = 0; g < 2; g++) {
                uint32_t bf[4];
                ldm_x4(bf, st + 16384 + off8(wn + g * 16 + lrow16, kb * 2 + lhi));
#pragma unroll
                for (int sub = 0; sub < 2; sub++) {
                    mma_f32(accg[g * 2 + sub], afh, bf[sub], bf[sub + 2]);
                    if (two)
                        mma_f32(accg[g * 2 + sub], afl, bf[sub], bf[sub + 2]);
                }
            }
        }

        // drain with per-n group scale
#pragma unroll
        for (int g = 0; g < 2; g++)
#pragma unroll
            for (int sub = 0; sub < 2; sub++) {
                const int nn = wn + g * 16 + sub * 8 + (lane & 3) * 2;
                const float s0 = ss[nn];
                const float s1 = ss[nn + 1];
                float* f = accf[g * 2 + sub];
                const float* a = accg[g * 2 + sub];
                f[0] += a[0] * s0;
                f[1] += a[1] * s1;
                f[2] += a[2] * s0;
                f[3] += a[3] * s1;
            }

        if (c + 2 < NC) load_stage(c + 2);
    }

    const int mrow = m0 + wm + (lane >> 2);
#pragma unroll
    for (int g = 0; g < 2; g++)
#pragma unroll
        for (int sub = 0; sub < 2; sub++) {
            const float* d = accf[g * 2 + sub];
            const int n = n0 + wn + g * 16 + sub * 8 + (lane & 3) * 2;
            *(float2*)(C + (size_t)mrow * ldc + n)       = make_float2(d[0], d[1]);
            *(float2*)(C + (size_t)(mrow + 8) * ldc + n) = make_float2(d[2], d[3]);
        }
}

// ---------------------------------------------------------------------------
// Output projection GEMM: fp16 att (1 term) x exact nibble weights.
// Same geometry: CTA 64x128, BK=64, 512 threads, 3-stage.
// ---------------------------------------------------------------------------
#define O_STAGE 24576          // A 8K | nib 16K
#define O_SMEM  (3 * O_STAGE + 3 * 512)

__global__ __launch_bounds__(512, 1) void gemm_o(
    const h16* __restrict__ A, const h16* __restrict__ Nib,
    const float* __restrict__ Sc, float* __restrict__ C)
{
    const int m0 = blockIdx.y * 64;
    const int n0 = blockIdx.x * 128;

    extern __shared__ char smem[];
    const uint32_t sb  = smem_u32(smem);
    const uint32_t ssc = sb + 3 * O_STAGE;
    const int tid  = threadIdx.x;
    const int wid  = tid >> 5;
    const int lane = tid & 31;

    const int NC = DM >> 6;
    const int wm = (wid & 3) * 16;
    const int wn = (wid >> 2) * 32;

    float accf[4][4];
#pragma unroll
    for (int j = 0; j < 4; j++)
#pragma unroll
        for (int v = 0; v < 4; v++) accf[j][v] = 0.0f;

    auto load_stage = [&](int c) {
        const int k0 = c << 6;
        const uint32_t st = sb + (uint32_t)(c % 3) * O_STAGE;
        {
            const int row = tid >> 3, kc = tid & 7;
            cp16(st + off8(row, kc), A + (size_t)(m0 + row) * DM + k0 + kc * 8);
        }
#pragma unroll
        for (int it = 0; it < 2; it++) {
            const int i = tid + it * 512;
            const int row = i >> 3, kc = i & 7;
            cp16(st + 8192 + off8(row, kc), Nib + (size_t)(n0 + row) * DM + k0 + kc * 8);
        }
        if (tid < 128)
            cp4(ssc + (uint32_t)(c % 3) * 512 + tid * 4,
                Sc + (size_t)(n0 + tid) * (DM >> 6) + c);
        cp_commit();
    };

    load_stage(0);
    load_stage(1);

    const int lrow16 = lane & 15;
    const int lhi    = lane >> 4;

    for (int c = 0; c < NC; c++) {
        if (c + 1 < NC) cp_wait<1>();
        else            cp_wait<0>();
        __syncthreads();

        const uint32_t st = sb + (uint32_t)(c % 3) * O_STAGE;
        const float* ss = (const float*)(smem + 3 * O_STAGE + (c % 3) * 512);

        float accg[4][4];
#pragma unroll
        for (int j = 0; j < 4; j++)
#pragma unroll
            for (int v = 0; v < 4; v++) accg[j][v] = 0.0f;

#pragma unroll
        for (int kb = 0; kb < 4; kb++) {
            uint32_t af[4];
            ldm_x4(af, st + off8(wm + lrow16, kb * 2 + lhi));
#pragma unroll
            for (int g = 0; g < 2; g++) {
                uint32_t bf[4];
                ldm_x4(bf, st + 8192 + off8(wn + g * 16 + lrow16, kb * 2 + lhi));
#pragma unroll
                for (int sub = 0; sub < 2; sub++)
                    mma_f32(accg[g * 2 + sub], af, bf[sub], bf[sub + 2]);
            }
        }

#pragma unroll
        for (int g = 0; g < 2; g++)
#pragma unroll
            for (int sub = 0; sub < 2; sub++) {
                const int nn = wn + g * 16 + sub * 8 + (lane & 3) * 2;
                const float s0 = ss[nn];
                const float s1 = ss[nn + 1];
                float* f = accf[g * 2 + sub];
                const float* a = accg[g * 2 + sub];
                f[0] += a[0] * s0;
                f[1] += a[1] * s1;
                f[2] += a[2] * s0;
                f[3] += a[3] * s1;
            }

        if (c + 2 < NC) load_stage(c + 2);
    }

    const int mrow = m0 + wm + (lane >> 2);
#pragma unroll
    for (int g = 0; g < 2; g++)
#pragma unroll
        for (int sub = 0; sub < 2; sub++) {
            const float* d = accf[g * 2 + sub];
            const int n = n0 + wn + g * 16 + sub * 8 + (lane & 3) * 2;
            *(float2*)(C + (size_t)mrow * DM + n)       = make_float2(d[0], d[1]);
            *(float2*)(C + (size_t)(mrow + 8) * DM + n) = make_float2(d[2], d[3]);
        }
}

// ---------------------------------------------------------------------------
// Fused flash attention: S = Q K^T (3-term split) -> online softmax -> O = P V.
// Grid (NH, 16 q-tiles, heavy first). 256 threads, 8 warps; warp = 16 q-rows
// x full 128-key tile.  Diagonal tiles skip key groups above the causal edge.
// ---------------------------------------------------------------------------
#define FA_QH 0
#define FA_QL 32768
#define FA_KH 65536
#define FA_KL 98304
#define FA_V0 131072
#define FA_V1 163840
#define FA_SMEM 196608

__global__ __launch_bounds__(256, 1) void flash_attn(
    const h16* __restrict__ Qh, const h16* __restrict__ Ql,
    const h16* __restrict__ Kh, const h16* __restrict__ Kl,
    const h16* __restrict__ Vt, h16* __restrict__ O)
{
    extern __shared__ char smem[];
    const uint32_t sb = smem_u32(smem);
    const int h   = blockIdx.x;
    const int qt  = gridDim.y - 1 - blockIdx.y;   // heavy tiles first
    const int kvh = h / (NH / NKV);
    const int tid = threadIdx.x;
    const int wid = tid >> 5;
    const int lane = tid & 31;
    const int NT = qt + 1;

    for (int i = tid; i < 2048; i += 256) {
        const int row = i >> 4, c = i & 15;
        const size_t g = (size_t)(qt * 128 + row) * DM + h * HD + c * 8;
        cp16(sb + FA_QH + off16(row, c), Qh + g);
        cp16(sb + FA_QL + off16(row, c), Ql + g);
    }
    cp_commit();
    for (int i = tid; i < 2048; i += 256) {
        const int row = i >> 4, c = i & 15;
        const size_t g = (size_t)row * KVD + kvh * HD + c * 8;
        cp16(sb + FA_KH + off16(row, c), Kh + g);
        cp16(sb + FA_KL + off16(row, c), Kl + g);
    }
    cp_commit();
    for (int i = tid; i < 2048; i += 256) {
        const int row = i >> 4, c = i & 15;
        cp16(sb + FA_V0 + off16(row, c), Vt + (size_t)(kvh * HD + row) * SEQ + c * 8);
    }
    cp_commit();
    cp_wait<1>();
    __syncthreads();

    const int g8     = lane >> 2;
    const int qd     = lane & 3;
    const int lrow16 = lane & 15;
    const int lhi    = lane >> 4;
    const int wq     = wid * 16;

    float of[16][4];
#pragma unroll
    for (int j = 0; j < 16; j++)
#pragma unroll
        for (int v = 0; v < 4; v++) of[j][v] = 0.0f;
    float m0 = -1e30f, m1 = -1e30f, l0 = 0.0f, l1 = 0.0f;

    for (int kt = 0; kt < NT; kt++) {
        const int gmax = (kt == qt) ? (wid + 1) : 8;   // causal key-group bound

        float    accf[16][4];
        uint32_t accc[16][2];
#pragma unroll
        for (int j = 0; j < 16; j++) {
#pragma unroll
            for (int v = 0; v < 4; v++) accf[j][v] = 0.0f;
            accc[j][0] = 0u; accc[j][1] = 0u;
        }

#pragma unroll
        for (int kb = 0; kb < 8; kb++) {
            uint32_t aqh[4], aql[4];
            const uint32_t aoff = off16(wq + lrow16, kb * 2 + lhi);
            ldm_x4(aqh, sb + FA_QH + aoff);
            ldm_x4(aql, sb + FA_QL + aoff);
#pragma unroll
            for (int g = 0; g < 8; g++) {
                if (g >= gmax) break;
                const uint32_t boff = off16(g * 16 + lrow16, kb * 2 + lhi);
                uint32_t bkh[4], bkl[4];
                ldm_x4(bkh, sb + FA_KH + boff);
                ldm_x4(bkl, sb + FA_KL + boff);
#pragma unroll
                for (int sub = 0; sub < 2; sub++) {
                    mma_f32(accf[g * 2 + sub], aqh, bkh[sub], bkh[sub + 2]);
                    mma_f16(accc[g * 2 + sub], aqh, bkl[sub], bkl[sub + 2]);
                    mma_f16(accc[g * 2 + sub], aql, bkh[sub], bkh[sub + 2]);
                }
            }
        }
#pragma unroll
        for (int j = 0; j < 16; j++) {
            const __half2 c0 = *(const __half2*)&accc[j][0];
            const __half2 c1 = *(const __half2*)&accc[j][1];
            accf[j][0] += __low2float(c0);
            accf[j][1] += __high2float(c0);
            accf[j][2] += __low2float(c1);
            accf[j][3] += __high2float(c1);
        }
        if (kt == qt) {
            const int r0 = wq + g8, r1 = r0 + 8;
#pragma unroll
            for (int j = 0; j < 16; j++) {
                const int cb = j * 8 + qd * 2;
                if (cb     > r0) accf[j][0] = -1e30f;
                if (cb + 1 > r0) accf[j][1] = -1e30f;
                if (cb     > r1) accf[j][2] = -1e30f;
                if (cb + 1 > r1) accf[j][3] = -1e30f;
            }
        }
        // ---- online softmax ----
        float mx0 = -1e30f, mx1 = -1e30f;
#pragma unroll
        for (int j = 0; j < 16; j++) {
            mx0 = fmaxf(mx0, fmaxf(accf[j][0], accf[j][1]));
            mx1 = fmaxf(mx1, fmaxf(accf[j][2], accf[j][3]));
        }
        mx0 = fmaxf(mx0, __shfl_xor_sync(0xffffffffu, mx0, 1));
        mx0 = fmaxf(mx0, __shfl_xor_sync(0xffffffffu, mx0, 2));
        mx1 = fmaxf(mx1, __shfl_xor_sync(0xffffffffu, mx1, 1));
        mx1 = fmaxf(mx1, __shfl_xor_sync(0xffffffffu, mx1, 2));

        const float nm0 = fmaxf(m0, mx0);
        const float nm1 = fmaxf(m1, mx1);
        const float sc0 = __expf(m0 - nm0);
        const float sc1 = __expf(m1 - nm1);
        float sum0 = 0.0f, sum1 = 0.0f;
#pragma unroll
        for (int j = 0; j < 16; j++) {
            accf[j][0] = __expf(accf[j][0] - nm0);
            accf[j][1] = __expf(accf[j][1] - nm0);
            accf[j][2] = __expf(accf[j][2] - nm1);
            accf[j][3] = __expf(accf[j][3] - nm1);
            sum0 += accf[j][0] + accf[j][1];
            sum1 += accf[j][2] + accf[j][3];
        }
        sum0 += __shfl_xor_sync(0xffffffffu, sum0, 1);
        sum0 += __shfl_xor_sync(0xffffffffu, sum0, 2);
        sum1 += __shfl_xor_sync(0xffffffffu, sum1, 1);
        sum1 += __shfl_xor_sync(0xffffffffu, sum1, 2);
        l0 = l0 * sc0 + sum0;
        l1 = l1 * sc1 + sum1;
        m0 = nm0;
        m1 = nm1;
#pragma unroll
        for (int j = 0; j < 16; j++) {
            of[j][0] *= sc0; of[j][1] *= sc0;
            of[j][2] *= sc1; of[j][3] *= sc1;
        }

        __syncthreads();

        const uint32_t vb = (kt & 1) ? FA_V1 : FA_V0;
        if (kt + 1 < NT) {
            const int kt1 = kt + 1;
            for (int i = tid; i < 2048; i += 256) {
                const int row = i >> 4, c = i & 15;
                const size_t g = (size_t)(kt1 * 128 + row) * KVD + kvh * HD + c * 8;
                cp16(sb + FA_KH + off16(row, c), Kh + g);
                cp16(sb + FA_KL + off16(row, c), Kl + g);
            }
            cp_commit();
            const uint32_t vb1 = (kt1 & 1) ? FA_V1 : FA_V0;
            for (int i = tid; i < 2048; i += 256) {
                const int row = i >> 4, c = i & 15;
                cp16(sb + vb1 + off16(row, c),
                     Vt + (size_t)(kvh * HD + row) * SEQ + kt1 * 128 + c * 8);
            }
            cp_commit();
            cp_wait<2>();
        } else {
            cp_wait<0>();
        }
        __syncthreads();

        // ---- O += P V (skip zero P chunks on diagonal) ----
#pragma unroll
        for (int c = 0; c < 8; c++) {
            if (c >= gmax) break;
            uint32_t pa[4];
            pa[0] = pack_h2(accf[2 * c][0],     accf[2 * c][1]);
            pa[1] = pack_h2(accf[2 * c][2],     accf[2 * c][3]);
            pa[2] = pack_h2(accf[2 * c + 1][0], accf[2 * c + 1][1]);
            pa[3] = pack_h2(accf[2 * c + 1][2], accf[2 * c + 1][3]);
#pragma unroll
            for (int gn = 0; gn < 8; gn++) {
                uint32_t bf[4];
                ldm_x4(bf, sb + vb + off16(gn * 16 + lrow16, c * 2 + lhi));
                mma_f32(of[gn * 2 + 0], pa, bf[0], bf[2]);
                mma_f32(of[gn * 2 + 1], pa, bf[1], bf[3]);
            }
        }

        if (kt + 1 < NT) { cp_wait<1>(); __syncthreads(); }
    }

    const float inv0 = 1.0f / l0;
    const float inv1 = 1.0f / l1;
    const int s0 = qt * 128 + wq + g8;
#pragma unroll
    for (int j = 0; j < 16; j++) {
        const int d = h * HD + j * 8 + qd * 2;
        *(__half2*)(O + (size_t)s0 * DM + d) =
            __floats2half2_rn(of[j][0] * inv0, of[j][1] * inv0);
        *(__half2*)(O + (size_t)(s0 + 8) * DM + d) =
            __floats2half2_rn(of[j][2] * inv1, of[j][3] * inv1);
    }
}

// ---------------------------------------------------------------------------
// Launch
// ---------------------------------------------------------------------------
extern "C" void kernel_launch(void* const* d_in, const int* in_sizes, int n_in,
                              void* d_out, int out_size)
{
    (void)in_sizes; (void)n_in; (void)out_size;
    const float* x    = (const float*)d_in[0];
    const void*  wq   = d_in[1];
    const float* sq   = (const float*)d_in[2];
    const void*  wk   = d_in[3];
    const float* sk   = (const float*)d_in[4];
    const void*  wv   = d_in[5];
    const float* sv   = (const float*)d_in[6];
    const void*  wo   = d_in[7];
    const float* so   = (const float*)d_in[8];
    const float* cosb = (const float*)d_in[9];
    const float* sinb = (const float*)d_in[10];
    float* out = (float*)d_out;

    float *xq, *xk, *xv;
    h16 *xh, *xl, *qh, *ql, *kh, *kl, *vth, *ath;
    h16 *nibq, *nibk, *nibv, *nibo;

    cudaGetSymbolAddress((void**)&xq,  g_xq);
    cudaGetSymbolAddress((void**)&xk,  g_xk);
    cudaGetSymbolAddress((void**)&xv,  g_xv);
    cudaGetSymbolAddress((void**)&xh,  g_xh);   cudaGetSymbolAddress((void**)&xl,  g_xl);
    cudaGetSymbolAddress((void**)&qh,  g_qh);   cudaGetSymbolAddress((void**)&ql,  g_ql);
    cudaGetSymbolAddress((void**)&kh,  g_kh);   cudaGetSymbolAddress((void**)&kl,  g_kl);
    cudaGetSymbolAddress((void**)&vth, g_vth);
    cudaGetSymbolAddress((void**)&ath, g_ath);
    cudaGetSymbolAddress((void**)&nibq, g_nibq); cudaGetSymbolAddress((void**)&nibk, g_nibk);
    cudaGetSymbolAddress((void**)&nibv, g_nibv); cudaGetSymbolAddress((void**)&nibo, g_nibo);

    cudaFuncSetAttribute(gemm_qkv,  cudaFuncAttributeMaxDynamicSharedMemorySize, QKV_SMEM);
    cudaFuncSetAttribute(gemm_o,    cudaFuncAttributeMaxDynamicSharedMemorySize, O_SMEM);
    cudaFuncSetAttribute(flash_attn, cudaFuncAttributeMaxDynamicSharedMemorySize, FA_SMEM);

    const dim3 blk(256);
    const dim3 blkG(512);

    // ingest; launch #6 = gemm_qkv (ncu window)
    probe_mode<<<1, 32>>>((const int*)wq);                                 // 1
    unpack_nib_h<<<2048, blk>>>(wq, nibq, (long)DM * DM);                  // 2
    split_f32<<<2048, blk>>>(x, xh, xl, (long)SEQ * DM);                   // 3
    unpack_nib_h<<<2048, blk>>>(wk, nibk, (long)KVD * DM);                 // 4
    unpack_nib_h<<<2048, blk>>>(wv, nibv, (long)KVD * DM);                 // 5
    gemm_qkv<<<dim3(48, SEQ / 64), blkG, QKV_SMEM>>>(                      // 6 (ncu)
        xh, xl, nibq, nibk, nibv, sq, sk, sv, xq, xk, xv);

    unpack_nib_h<<<2048, blk>>>(wo, nibo, (long)DM * DM);

    rope_split<<<(SEQ * NH  * 64 + 255) / 256, blk>>>(xq, cosb, sinb, qh, ql, NH,
                                                      0.08838834764831843f);
    rope_split<<<(SEQ * NKV * 64 + 255) / 256, blk>>>(xk, cosb, sinb, kh, kl, NKV, 1.0f);
    vtrans_h<<<(NKV * HD * SEQ + 255) / 256, blk>>>(xv, vth);

    // fused attention: QK^T (3-term) + online softmax + PV -> fp16 att
    flash_attn<<<dim3(NH, SEQ / 128), blk, FA_SMEM>>>(qh, ql, kh, kl, vth, ath);

    // output projection (1-term, exact weights)
    gemm_o<<<dim3(DM / 128, SEQ / 64), blkG, O_SMEM>>>(ath, nibo, so, out);
}

// round 14
// speedup vs baseline: 1.1124x; 1.1124x over previous
#include <cuda_runtime.h>
#include <cuda_fp16.h>
#include <cstdint>
#include <cstring>

// ---------------------------------------------------------------------------
// Problem constants
// ---------------------------------------------------------------------------
#define SEQ   2048
#define DM    4096
#define NH    32
#define NKV   8
#define HD    128
#define KVD   (NKV * HD)   // 1024

typedef __half h16;

// ---------------------------------------------------------------------------
// Device-global scratch (allocation-free rule)
// ---------------------------------------------------------------------------
__device__ float g_xq[SEQ * DM];
__device__ float g_xk[SEQ * KVD];
__device__ float g_xv[SEQ * KVD];

__device__ __align__(16) h16 g_xh [SEQ * DM],  g_xl [SEQ * DM];  // x split
__device__ __align__(16) h16 g_qh [SEQ * DM],  g_ql [SEQ * DM];  // q split
__device__ __align__(16) h16 g_kh [SEQ * KVD], g_kl [SEQ * KVD]; // k split
__device__ __align__(16) h16 g_vth[NKV * HD * SEQ];              // V^T plain
__device__ __align__(16) h16 g_ath[SEQ * DM];                    // attention out

// exact fp16 nibble planes (weight = nib * group_scale)
__device__ __align__(16) h16 g_nibq[DM * DM];
__device__ __align__(16) h16 g_nibk[KVD * DM];
__device__ __align__(16) h16 g_nibv[KVD * DM];
__device__ __align__(16) h16 g_nibo[DM * DM];

__device__ int g_mode;

// ---------------------------------------------------------------------------
// PTX helpers (base sm_103 ISA: cp.async / ldmatrix / mma.sync)
// ---------------------------------------------------------------------------
__device__ __forceinline__ uint32_t smem_u32(const void* p) {
    uint32_t a;
    asm("{ .reg .u64 t; cvta.to.shared.u64 t, %1; cvt.u32.u64 %0, t; }" : "=r"(a) : "l"(p));
    return a;
}
__device__ __forceinline__ void cp16(uint32_t dst, const void* src) {
    asm volatile("cp.async.cg.shared.global [%0], [%1], 16;" :: "r"(dst), "l"(src) : "memory");
}
__device__ __forceinline__ void cp4(uint32_t dst, const void* src) {
    asm volatile("cp.async.ca.shared.global [%0], [%1], 4;" :: "r"(dst), "l"(src) : "memory");
}
__device__ __forceinline__ void cp_commit() {
    asm volatile("cp.async.commit_group;" ::: "memory");
}
template <int N>
__device__ __forceinline__ void cp_wait() {
    asm volatile("cp.async.wait_group %0;" :: "n"(N) : "memory");
}
__device__ __forceinline__ void ldm_x4(uint32_t* r, uint32_t addr) {
    asm volatile("ldmatrix.sync.aligned.m8n8.x4.shared.b16 {%0,%1,%2,%3}, [%4];"
                 : "=r"(r[0]), "=r"(r[1]), "=r"(r[2]), "=r"(r[3]) : "r"(addr));
}
__device__ __forceinline__ void mma_f32(float* d, const uint32_t* a,
                                        uint32_t b0, uint32_t b1) {
    asm volatile(
        "mma.sync.aligned.m16n8k16.row.col.f32.f16.f16.f32 "
        "{%0,%1,%2,%3}, {%4,%5,%6,%7}, {%8,%9}, {%0,%1,%2,%3};"
        : "+f"(d[0]), "+f"(d[1]), "+f"(d[2]), "+f"(d[3])
        : "r"(a[0]), "r"(a[1]), "r"(a[2]), "r"(a[3]), "r"(b0), "r"(b1));
}
__device__ __forceinline__ void mma_f16(uint32_t* d, const uint32_t* a,
                                        uint32_t b0, uint32_t b1) {
    asm volatile(
        "mma.sync.aligned.m16n8k16.row.col.f16.f16.f16.f16 "
        "{%0,%1}, {%2,%3,%4,%5}, {%6,%7}, {%0,%1};"
        : "+r"(d[0]), "+r"(d[1])
        : "r"(a[0]), "r"(a[1]), "r"(a[2]), "r"(a[3]), "r"(b0), "r"(b1));
}

// Pack two floats into one uint32 holding an fp16 pair (BOTH halves).
__device__ __forceinline__ uint32_t pack_h2(float a, float b) {
    __half2 t = __floats2half2_rn(a, b);
    uint32_t r;
    memcpy(&r, &t, 4);
    return r;
}

// Permuted conflict-free smem layouts: atom = 8 rows x 16B, 128B blocks.
__device__ __forceinline__ uint32_t off8(int row, int kc) {   // 64-wide fp16 tile
    return (uint32_t)((((row >> 3) * 8 + kc) << 7) + ((row & 7) << 4));
}
__device__ __forceinline__ uint32_t off16(int row, int kc) {  // 128-wide fp16 tile
    return (uint32_t)((((row >> 3) * 16 + kc) << 7) + ((row & 7) << 4));
}

// ---------------------------------------------------------------------------
// Probe (dtype-robust weight ingestion)
// ---------------------------------------------------------------------------
__global__ void probe_mode(const int* __restrict__ w)
{
    if (threadIdx.x == 0 && blockIdx.x == 0) {
        int ok = 0;
        for (int i = 0; i < 256; i++) {
            const int v = w[i];
            if (v >= -128 && v <= 127) ok++;
        }
        g_mode = (ok >= 250) ? 1 : 0;
    }
}

// Unpack Q4_0 nibbles directly from raw input (mode-aware) to fp16 planes.
__global__ __launch_bounds__(256) void unpack_nib_h(
    const void* __restrict__ in, h16* __restrict__ nib, long n)
{
    const int mode = g_mode;
    const long stride = (long)gridDim.x * blockDim.x;
    for (long f = (long)blockIdx.x * blockDim.x + threadIdx.x; f < n; f += stride) {
        const int  q = (int)(f & 127);
        const long b = (f >> 7) * 64 + (q & 63);
        const int8_t raw = mode ? (int8_t)((const int*)in)[b]
                                : ((const int8_t*)in)[b];
        const int v = (q < 64) ? (raw >> 4) : (((int8_t)(raw << 4)) >> 4);
        nib[f] = __float2half((float)v);
    }
}

// fp32 -> fp16 hi/lo split
__global__ __launch_bounds__(256) void split_f32(
    const float* __restrict__ src, h16* __restrict__ hi, h16* __restrict__ lo, long n)
{
    const long stride = (long)gridDim.x * blockDim.x;
    for (long i = (long)blockIdx.x * blockDim.x + threadIdx.x; i < n; i += stride) {
        const float v = src[i];
        const h16 h = __float2half(v);
        hi[i] = h;
        lo[i] = __float2half(v - __half2float(h));
    }
}

// ---------------------------------------------------------------------------
// RoPE (rotate-half) + optional scale + fp16 split.  x laid out [S, nh, HD].
// ---------------------------------------------------------------------------
__global__ __launch_bounds__(256) void rope_split(
    const float* __restrict__ x, const float* __restrict__ cosb,
    const float* __restrict__ sinb, h16* __restrict__ oh, h16* __restrict__ ol,
    int nheads, float scale)
{
    const long total = (long)SEQ * nheads * 64;
    long idx = (long)blockIdx.x * blockDim.x + threadIdx.x;
    if (idx >= total) return;
    const int d = (int)(idx & 63);
    const int h = (int)((idx >> 6) % nheads);
    const int s = (int)(idx / ((long)64 * nheads));
    const size_t base = (size_t)s * nheads * HD + h * HD + d;
    const float c  = cosb[s * 64 + d];
    const float sn = sinb[s * 64 + d];
    const float lo = x[base];
    const float hi = x[base + 64];
    const float r0 = (lo * c - hi * sn) * scale;
    const float r1 = (hi * c + lo * sn) * scale;
    h16 h0 = __float2half(r0);
    h16 h1 = __float2half(r1);
    oh[base]      = h0;
    ol[base]      = __float2half(r0 - __half2float(h0));
    oh[base + 64] = h1;
    ol[base + 64] = __float2half(r1 - __half2float(h1));
}

// ---------------------------------------------------------------------------
// Transpose V to plain fp16: vt[kv][d][s] = xv[s][kv*HD + d]
// ---------------------------------------------------------------------------
__global__ __launch_bounds__(256) void vtrans_h(
    const float* __restrict__ xv, h16* __restrict__ vt)
{
    const long total = (long)NKV * HD * SEQ;
    long idx = (long)blockIdx.x * blockDim.x + threadIdx.x;
    if (idx >= total) return;
    const int s  = (int)(idx % SEQ);
    const int d  = (int)((idx / SEQ) % HD);
    const int kv = (int)(idx / ((long)SEQ * HD));
    vt[idx] = __float2half(xv[(size_t)s * KVD + kv * HD + d]);
}

// ---------------------------------------------------------------------------
// Merged QKV projection GEMM at full 128x128 CTA tiles.
// 512 threads, 16 warps 4x4, warp tile 32x32, BK=64, 3-stage cp.async.
// 1-D grid, 768 CTAs: [0,512) q (2-term), [512,640) k (2-term),
// [640,768) v (1-term, light, scheduled last).
// Weight = fp16 nibble (exact) * fp32 group scale drained per BK=64 group.
// ---------------------------------------------------------------------------
#define W4_TILE  16384                        // 128 x 64 fp16
#define W4_STAGE (3 * W4_TILE)                // Ah | Al | nib : 48 KB
#define W4_SMEM  (3 * W4_STAGE + 3 * 512)

__global__ __launch_bounds__(512, 1) void gemm_qkv(
    const h16* __restrict__ xh, const h16* __restrict__ xl,
    const h16* __restrict__ nq, const h16* __restrict__ nk,
    const h16* __restrict__ nv,
    const float* __restrict__ sq, const float* __restrict__ sk,
    const float* __restrict__ sv,
    float* __restrict__ xq, float* __restrict__ xk, float* __restrict__ xv)
{
    const int bx = blockIdx.x;
    const h16* Nib;
    const float* Sc;
    float* C;
    int ldc, n0, m0, two;
    if (bx < 512) {
        Nib = nq; Sc = sq; C = xq; ldc = DM; two = 1;
        n0 = (bx & 31) * 128; m0 = (bx >> 5) * 128;
    } else if (bx < 640) {
        const int i = bx - 512;
        Nib = nk; Sc = sk; C = xk; ldc = KVD; two = 1;
        n0 = (i & 7) * 128; m0 = (i >> 3) * 128;
    } else {
        const int i = bx - 640;
        Nib = nv; Sc = sv; C = xv; ldc = KVD; two = 0;
        n0 = (i & 7) * 128; m0 = (i >> 3) * 128;
    }

    extern __shared__ char smem[];
    const uint32_t sb  = smem_u32(smem);
    const uint32_t ssc = sb + 3 * W4_STAGE;
    const int tid  = threadIdx.x;
    const int wid  = tid >> 5;
    const int lane = tid & 31;

    const int NC = DM >> 6;
    const int KG = DM >> 6;

    const int wm = (wid & 3) * 32;
    const int wn = (wid >> 2) * 32;

    float accf[2][4][4];
#pragma unroll
    for (int i = 0; i < 2; i++)
#pragma unroll
        for (int j = 0; j < 4; j++)
#pragma unroll
            for (int v = 0; v < 4; v++) accf[i][j][v] = 0.0f;

    auto load_stage = [&](int c) {
        const int k0 = c << 6;
        const uint32_t st = sb + (uint32_t)(c % 3) * W4_STAGE;
        // Ah + nib always (2048 cp16), Al only when two (1024 cp16)
        const int total = (two ? 3 : 2) << 10;
        for (int i = tid; i < total; i += 512) {
            const int tile = i >> 10;
            const int row  = (i >> 3) & 127;
            const int kc   = i & 7;
            const h16* src;
            uint32_t dstb;
            if (tile == 0)             { src = xh  + (size_t)(m0 + row) * DM + k0; dstb = st; }
            else if (two && tile == 1) { src = xl  + (size_t)(m0 + row) * DM + k0; dstb = st + W4_TILE; }
            else                       { src = Nib + (size_t)(n0 + row) * DM + k0; dstb = st + 2 * W4_TILE; }
            cp16(dstb + off8(row, kc), src + kc * 8);
        }
        if (tid < 128)
            cp4(ssc + (uint32_t)(c % 3) * 512 + tid * 4,
                Sc + (size_t)(n0 + tid) * KG + c);
        cp_commit();
    };

    load_stage(0);
    load_stage(1);

    const int lrow16 = lane & 15;
    const int lhi    = lane >> 4;

    for (int c = 0; c < NC; c++) {
        if (c + 1 < NC) cp_wait<1>();
        else            cp_wait<0>();
        __syncthreads();

        const uint32_t st = sb + (uint32_t)(c % 3) * W4_STAGE;
        const float* ss = (const float*)(smem + 3 * W4_STAGE + (c % 3) * 512);

        float accg[2][4][4];
#pragma unroll
        for (int i = 0; i < 2; i++)
#pragma unroll
            for (int j = 0; j < 4; j++)
#pragma unroll
                for (int v = 0; v < 4; v++) accg[i][j][v] = 0.0f;

#pragma unroll
        for (int kb = 0; kb < 4; kb++) {
            uint32_t afh[2][4], afl[2][4];
#pragma unroll
            for (int mt = 0; mt < 2; mt++) {
                const uint32_t off = off8(wm + mt * 16 + lrow16, kb * 2 + lhi);
                ldm_x4(afh[mt], st + off);
                if (two) ldm_x4(afl[mt], st + W4_TILE + off);
            }
#pragma unroll
            for (int g = 0; g < 2; g++) {
                uint32_t bf[4];
                ldm_x4(bf, st + 2 * W4_TILE + off8(wn + g * 16 + lrow16, kb * 2 + lhi));
#pragma unroll
                for (int mt = 0; mt < 2; mt++) {
#pragma unroll
                    for (int sub = 0; sub < 2; sub++) {
                        mma_f32(accg[mt][g * 2 + sub], afh[mt], bf[sub], bf[sub + 2]);
                        if (two)
                            mma_f32(accg[mt][g * 2 + sub], afl[mt], bf[sub], bf[sub + 2]);
                    }
                }
            }
        }

        // drain group acc with per-n scale
#pragma unroll
        for (int g = 0; g < 2; g++)
#pragma unroll
            for (int sub = 0; sub < 2; sub++) {
                const int nn = wn + g * 16 + sub * 8 + (lane & 3) * 2;
                const float s0 = ss[nn];
                const float s1 = ss[nn + 1];
#pragma unroll
                for (int mt = 0; mt < 2; mt++) {
                    float* f = accf[mt][g * 2 + sub];
                    const float* a = accg[mt][g * 2 + sub];
                    f[0] += a[0] * s0;
                    f[1] += a[1] * s1;
                    f[2] += a[2] * s0;
                    f[3] += a[3] * s1;
                }
            }

        if (c + 2 < NC) load_stage(c + 2);
    }

#pragma unroll
    for (int mt = 0; mt < 2; mt++) {
        const int mrow = m0 + wm + mt * 16 + (lane >> 2);
#pragma unroll
        for (int g = 0; g < 2; g++)
#pragma unroll
            for (int sub = 0; sub < 2; sub++) {
                const float* d = accf[mt][g * 2 + sub];
                const int n = n0 + wn + g * 16 + sub * 8 + (lane & 3) * 2;
                *(float2*)(C + (size_t)mrow * ldc + n)       = make_float2(d[0], d[1]);
                *(float2*)(C + (size_t)(mrow + 8) * ldc + n) = make_float2(d[2], d[3]);
            }
    }
}

// ---------------------------------------------------------------------------
// Output projection GEMM (1-term, exact nibble weights): round-11 geometry.
// 512 threads, 16 warps 4x4, warp 32x32, CTA 128x128, BK=64, 3-stage.
// ---------------------------------------------------------------------------
#define O_STAGE (2 * W4_TILE)            // A | nib : 32 KB
#define O_SMEM  (3 * O_STAGE + 3 * 512)

__global__ __launch_bounds__(512, 1) void gemm_o(
    const h16* __restrict__ A, const h16* __restrict__ Nib,
    const float* __restrict__ Sc, float* __restrict__ C)
{
    const int m0 = blockIdx.y * 128;
    const int n0 = blockIdx.x * 128;

    extern __shared__ char smem[];
    const uint32_t sb  = smem_u32(smem);
    const uint32_t ssc = sb + 3 * O_STAGE;
    const int tid  = threadIdx.x;
    const int wid  = tid >> 5;
    const int lane = tid & 31;

    const int NC = DM >> 6;
    const int KG = DM >> 6;

    const int wm = (wid & 3) * 32;
    const int wn = (wid >> 2) * 32;

    float accf[2][4][4];
#pragma unroll
    for (int i = 0; i < 2; i++)
#pragma unroll
        for (int j = 0; j < 4; j++)
#pragma unroll
            for (int v = 0; v < 4; v++) accf[i][j][v] = 0.0f;

    auto load_stage = [&](int c) {
        const int k0 = c << 6;
        const uint32_t st = sb + (uint32_t)(c % 3) * O_STAGE;
        for (int i = tid; i < 2048; i += 512) {
            const int tile = i >> 10;
            const int row  = (i >> 3) & 127;
            const int kc   = i & 7;
            const h16* src = tile ? (Nib + (size_t)(n0 + row) * DM + k0)
                                  : (A   + (size_t)(m0 + row) * DM + k0);
            cp16(st + (uint32_t)tile * W4_TILE + off8(row, kc), src + kc * 8);
        }
        if (tid < 128)
            cp4(ssc + (uint32_t)(c % 3) * 512 + tid * 4,
                Sc + (size_t)(n0 + tid) * KG + c);
        cp_commit();
    };

    load_stage(0);
    load_stage(1);

    const int lrow16 = lane & 15;
    const int lhi    = lane >> 4;

    for (int c = 0; c < NC; c++) {
        if (c + 1 < NC) cp_wait<1>();
        else            cp_wait<0>();
        __syncthreads();

        const uint32_t st = sb + (uint32_t)(c % 3) * O_STAGE;
        const float* ss = (const float*)(smem + 3 * O_STAGE + (c % 3) * 512);

        float accg[2][4][4];
#pragma unroll
        for (int i = 0; i < 2; i++)
#pragma unroll
            for (int j = 0; j < 4; j++)
#pragma unroll
                for (int v = 0; v < 4; v++) accg[i][j][v] = 0.0f;

#pragma unroll
        for (int kb = 0; kb < 4; kb++) {
            uint32_t af[2][4];
#pragma unroll
            for (int mt = 0; mt < 2; mt++)
                ldm_x4(af[mt], st + off8(wm + mt * 16 + lrow16, kb * 2 + lhi));
#pragma unroll
            for (int g = 0; g < 2; g++) {
                uint32_t bf[4];
                ldm_x4(bf, st + W4_TILE + off8(wn + g * 16 + lrow16, kb * 2 + lhi));
#pragma unroll
                for (int mt = 0; mt < 2; mt++) {
#pragma unroll
                    for (int sub = 0; sub < 2; sub++)
                        mma_f32(accg[mt][g * 2 + sub], af[mt], bf[sub], bf[sub + 2]);
                }
            }
        }

#pragma unroll
        for (int g = 0; g < 2; g++)
#pragma unroll
            for (int sub = 0; sub < 2; sub++) {
                const int nn = wn + g * 16 + sub * 8 + (lane & 3) * 2;
                const float s0 = ss[nn];
                const float s1 = ss[nn + 1];
#pragma unroll
                for (int mt = 0; mt < 2; mt++) {
                    float* f = accf[mt][g * 2 + sub];
                    const float* a = accg[mt][g * 2 + sub];
                    f[0] += a[0] * s0;
                    f[1] += a[1] * s1;
                    f[2] += a[2] * s0;
                    f[3] += a[3] * s1;
                }
            }

        if (c + 2 < NC) load_stage(c + 2);
    }

#pragma unroll
    for (int mt = 0; mt < 2; mt++) {
        const int mrow = m0 + wm + mt * 16 + (lane >> 2);
#pragma unroll
        for (int g = 0; g < 2; g++)
#pragma unroll
            for (int sub = 0; sub < 2; sub++) {
                const float* d = accf[mt][g * 2 + sub];
                const int n = n0 + wn + g * 16 + sub * 8 + (lane & 3) * 2;
                *(float2*)(C + (size_t)mrow * DM + n)       = make_float2(d[0], d[1]);
                *(float2*)(C + (size_t)(mrow + 8) * DM + n) = make_float2(d[2], d[3]);
            }
    }
}

// ---------------------------------------------------------------------------
// Fused flash attention: S = Q K^T (3-term split) -> online softmax -> O = P V.
// Grid (NH, 16 q-tiles, heavy first). 256 threads, 8 warps; warp = 16 q-rows
// x full 128-key tile.  Diagonal tiles skip key groups above the causal edge.
// ---------------------------------------------------------------------------
#define FA_QH 0
#define FA_QL 32768
#define FA_KH 65536
#define FA_KL 98304
#define FA_V0 131072
#define FA_V1 163840
#define FA_SMEM 196608

__global__ __launch_bounds__(256, 1) void flash_attn(
    const h16* __restrict__ Qh, const h16* __restrict__ Ql,
    const h16* __restrict__ Kh, const h16* __restrict__ Kl,
    const h16* __restrict__ Vt, h16* __restrict__ O)
{
    extern __shared__ char smem[];
    const uint32_t sb = smem_u32(smem);
    const int h   = blockIdx.x;
    const int qt  = gridDim.y - 1 - blockIdx.y;   // heavy tiles first
    const int kvh = h / (NH / NKV);
    const int tid = threadIdx.x;
    const int wid = tid >> 5;
    const int lane = tid & 31;
    const int NT = qt + 1;

    for (int i = tid; i < 2048; i += 256) {
        const int row = i >> 4, c = i & 15;
        const size_t g = (size_t)(qt * 128 + row) * DM + h * HD + c * 8;
        cp16(sb + FA_QH + off16(row, c), Qh + g);
        cp16(sb + FA_QL + off16(row, c), Ql + g);
    }
    cp_commit();
    for (int i = tid; i < 2048; i += 256) {
        const int row = i >> 4, c = i & 15;
        const size_t g = (size_t)row * KVD + kvh * HD + c * 8;
        cp16(sb + FA_KH + off16(row, c), Kh + g);
        cp16(sb + FA_KL + off16(row, c), Kl + g);
    }
    cp_commit();
    for (int i = tid; i < 2048; i += 256) {
        const int row = i >> 4, c = i & 15;
        cp16(sb + FA_V0 + off16(row, c), Vt + (size_t)(kvh * HD + row) * SEQ + c * 8);
    }
    cp_commit();
    cp_wait<1>();
    __syncthreads();

    const int g8     = lane >> 2;
    const int qd     = lane & 3;
    const int lrow16 = lane & 15;
    const int lhi    = lane >> 4;
    const int wq     = wid * 16;

    float of[16][4];
#pragma unroll
    for (int j = 0; j < 16; j++)
#pragma unroll
        for (int v = 0; v < 4; v++) of[j][v] = 0.0f;
    float m0 = -1e30f, m1 = -1e30f, l0 = 0.0f, l1 = 0.0f;

    for (int kt = 0; kt < NT; kt++) {
        const int gmax = (kt == qt) ? (wid + 1) : 8;   // causal key-group bound

        float    accf[16][4];
        uint32_t accc[16][2];
#pragma unroll
        for (int j = 0; j < 16; j++) {
#pragma unroll
            for (int v = 0; v < 4; v++) accf[j][v] = 0.0f;
            accc[j][0] = 0u; accc[j][1] = 0u;
        }

#pragma unroll
        for (int kb = 0; kb < 8; kb++) {
            uint32_t aqh[4], aql[4];
            const uint32_t aoff = off16(wq + lrow16, kb * 2 + lhi);
            ldm_x4(aqh, sb + FA_QH + aoff);
            ldm_x4(aql, sb + FA_QL + aoff);
#pragma unroll
            for (int g = 0; g < 8; g++) {
                if (g >= gmax) break;
                const uint32_t boff = off16(g * 16 + lrow16, kb * 2 + lhi);
                uint32_t bkh[4], bkl[4];
                ldm_x4(bkh, sb + FA_KH + boff);
                ldm_x4(bkl, sb + FA_KL + boff);
#pragma unroll
                for (int sub = 0; sub < 2; sub++) {
                    mma_f32(accf[g * 2 + sub], aqh, bkh[sub], bkh[sub + 2]);
                    mma_f16(accc[g * 2 + sub], aqh, bkl[sub], bkl[sub + 2]);
                    mma_f16(accc[g * 2 + sub], aql, bkh[sub], bkh[sub + 2]);
                }
            }
        }
#pragma unroll
        for (int j = 0; j < 16; j++) {
            const __half2 c0 = *(const __half2*)&accc[j][0];
            const __half2 c1 = *(const __half2*)&accc[j][1];
            accf[j][0] += __low2float(c0);
            accf[j][1] += __high2float(c0);
            accf[j][2] += __low2float(c1);
            accf[j][3] += __high2float(c1);
        }
        if (kt == qt) {
            const int r0 = wq + g8, r1 = r0 + 8;
#pragma unroll
            for (int j = 0; j < 16; j++) {
                const int cb = j * 8 + qd * 2;
                if (cb     > r0) accf[j][0] = -1e30f;
                if (cb + 1 > r0) accf[j][1] = -1e30f;
                if (cb     > r1) accf[j][2] = -1e30f;
                if (cb + 1 > r1) accf[j][3] = -1e30f;
            }
        }
        // ---- online softmax ----
        float mx0 = -1e30f, mx1 = -1e30f;
#pragma unroll
        for (int j = 0; j < 16; j++) {
            mx0 = fmaxf(mx0, fmaxf(accf[j][0], accf[j][1]));
            mx1 = fmaxf(mx1, fmaxf(accf[j][2], accf[j][3]));
        }
        mx0 = fmaxf(mx0, __shfl_xor_sync(0xffffffffu, mx0, 1));
        mx0 = fmaxf(mx0, __shfl_xor_sync(0xffffffffu, mx0, 2));
        mx1 = fmaxf(mx1, __shfl_xor_sync(0xffffffffu, mx1, 1));
        mx1 = fmaxf(mx1, __shfl_xor_sync(0xffffffffu, mx1, 2));

        const float nm0 = fmaxf(m0, mx0);
        const float nm1 = fmaxf(m1, mx1);
        const float sc0 = __expf(m0 - nm0);
        const float sc1 = __expf(m1 - nm1);
        float sum0 = 0.0f, sum1 = 0.0f;
#pragma unroll
        for (int j = 0; j < 16; j++) {
            accf[j][0] = __expf(accf[j][0] - nm0);
            accf[j][1] = __expf(accf[j][1] - nm0);
            accf[j][2] = __expf(accf[j][2] - nm1);
            accf[j][3] = __expf(accf[j][3] - nm1);
            sum0 += accf[j][0] + accf[j][1];
            sum1 += accf[j][2] + accf[j][3];
        }
        sum0 += __shfl_xor_sync(0xffffffffu, sum0, 1);
        sum0 += __shfl_xor_sync(0xffffffffu, sum0, 2);
        sum1 += __shfl_xor_sync(0xffffffffu, sum1, 1);
        sum1 += __shfl_xor_sync(0xffffffffu, sum1, 2);
        l0 = l0 * sc0 + sum0;
        l1 = l1 * sc1 + sum1;
        m0 = nm0;
        m1 = nm1;
#pragma unroll
        for (int j = 0; j < 16; j++) {
            of[j][0] *= sc0; of[j][1] *= sc0;
            of[j][2] *= sc1; of[j][3] *= sc1;
        }

        __syncthreads();

        const uint32_t vb = (kt & 1) ? FA_V1 : FA_V0;
        if (kt + 1 < NT) {
            const int kt1 = kt + 1;
            for (int i = tid; i < 2048; i += 256) {
                const int row = i >> 4, c = i & 15;
                const size_t g = (size_t)(kt1 * 128 + row) * KVD + kvh * HD + c * 8;
                cp16(sb + FA_KH + off16(row, c), Kh + g);
                cp16(sb + FA_KL + off16(row, c), Kl + g);
            }
            cp_commit();
            const uint32_t vb1 = (kt1 & 1) ? FA_V1 : FA_V0;
            for (int i = tid; i < 2048; i += 256) {
                const int row = i >> 4, c = i & 15;
                cp16(sb + vb1 + off16(row, c),
                     Vt + (size_t)(kvh * HD + row) * SEQ + kt1 * 128 + c * 8);
            }
            cp_commit();
            cp_wait<2>();
        } else {
            cp_wait<0>();
        }
        __syncthreads();

        // ---- O += P V (skip zero P chunks on diagonal) ----
#pragma unroll
        for (int c = 0; c < 8; c++) {
            if (c >= gmax) break;
            uint32_t pa[4];
            pa[0] = pack_h2(accf[2 * c][0],     accf[2 * c][1]);
            pa[1] = pack_h2(accf[2 * c][2],     accf[2 * c][3]);
            pa[2] = pack_h2(accf[2 * c + 1][0], accf[2 * c + 1][1]);
            pa[3] = pack_h2(accf[2 * c + 1][2], accf[2 * c + 1][3]);
#pragma unroll
            for (int gn = 0; gn < 8; gn++) {
                uint32_t bf[4];
                ldm_x4(bf, sb + vb + off16(gn * 16 + lrow16, c * 2 + lhi));
                mma_f32(of[gn * 2 + 0], pa, bf[0], bf[2]);
                mma_f32(of[gn * 2 + 1], pa, bf[1], bf[3]);
            }
        }

        if (kt + 1 < NT) { cp_wait<1>(); __syncthreads(); }
    }

    const float inv0 = 1.0f / l0;
    const float inv1 = 1.0f / l1;
    const int s0 = qt * 128 + wq + g8;
#pragma unroll
    for (int j = 0; j < 16; j++) {
        const int d = h * HD + j * 8 + qd * 2;
        *(__half2*)(O + (size_t)s0 * DM + d) =
            __floats2half2_rn(of[j][0] * inv0, of[j][1] * inv0);
        *(__half2*)(O + (size_t)(s0 + 8) * DM + d) =
            __floats2half2_rn(of[j][2] * inv1, of[j][3] * inv1);
    }
}

// ---------------------------------------------------------------------------
// Launch
// ---------------------------------------------------------------------------
extern "C" void kernel_launch(void* const* d_in, const int* in_sizes, int n_in,
                              void* d_out, int out_size)
{
    (void)in_sizes; (void)n_in; (void)out_size;
    const float* x    = (const float*)d_in[0];
    const void*  wq   = d_in[1];
    const float* sq   = (const float*)d_in[2];
    const void*  wk   = d_in[3];
    const float* sk   = (const float*)d_in[4];
    const void*  wv   = d_in[5];
    const float* sv   = (const float*)d_in[6];
    const void*  wo   = d_in[7];
    const float* so   = (const float*)d_in[8];
    const float* cosb = (const float*)d_in[9];
    const float* sinb = (const float*)d_in[10];
    float* out = (float*)d_out;

    float *xq, *xk, *xv;
    h16 *xh, *xl, *qh, *ql, *kh, *kl, *vth, *ath;
    h16 *nibq, *nibk, *nibv, *nibo;

    cudaGetSymbolAddress((void**)&xq,  g_xq);
    cudaGetSymbolAddress((void**)&xk,  g_xk);
    cudaGetSymbolAddress((void**)&xv,  g_xv);
    cudaGetSymbolAddress((void**)&xh,  g_xh);   cudaGetSymbolAddress((void**)&xl,  g_xl);
    cudaGetSymbolAddress((void**)&qh,  g_qh);   cudaGetSymbolAddress((void**)&ql,  g_ql);
    cudaGetSymbolAddress((void**)&kh,  g_kh);   cudaGetSymbolAddress((void**)&kl,  g_kl);
    cudaGetSymbolAddress((void**)&vth, g_vth);
    cudaGetSymbolAddress((void**)&ath, g_ath);
    cudaGetSymbolAddress((void**)&nibq, g_nibq); cudaGetSymbolAddress((void**)&nibk, g_nibk);
    cudaGetSymbolAddress((void**)&nibv, g_nibv); cudaGetSymbolAddress((void**)&nibo, g_nibo);

    cudaFuncSetAttribute(gemm_qkv,  cudaFuncAttributeMaxDynamicSharedMemorySize, W4_SMEM);
    cudaFuncSetAttribute(gemm_o,    cudaFuncAttributeMaxDynamicSharedMemorySize, O_SMEM);
    cudaFuncSetAttribute(flash_attn, cudaFuncAttributeMaxDynamicSharedMemorySize, FA_SMEM);

    const dim3 blk(256);
    const dim3 blkG(512);

    // ingest; launch #6 = gemm_qkv (ncu window)
    probe_mode<<<1, 32>>>((const int*)wq);                                 // 1
    unpack_nib_h<<<2048, blk>>>(wq, nibq, (long)DM * DM);                  // 2
    split_f32<<<2048, blk>>>(x, xh, xl, (long)SEQ * DM);                   // 3
    unpack_nib_h<<<2048, blk>>>(wk, nibk, (long)KVD * DM);                 // 4
    unpack_nib_h<<<2048, blk>>>(wv, nibv, (long)KVD * DM);                 // 5
    gemm_qkv<<<768, blkG, W4_SMEM>>>(                                      // 6 (ncu)
        xh, xl, nibq, nibk, nibv, sq, sk, sv, xq, xk, xv);

    unpack_nib_h<<<2048, blk>>>(wo, nibo, (long)DM * DM);

    rope_split<<<(SEQ * NH  * 64 + 255) / 256, blk>>>(xq, cosb, sinb, qh, ql, NH,
                                                      0.08838834764831843f);
    rope_split<<<(SEQ * NKV * 64 + 255) / 256, blk>>>(xk, cosb, sinb, kh, kl, NKV, 1.0f);
    vtrans_h<<<(NKV * HD * SEQ + 255) / 256, blk>>>(xv, vth);

    // fused attention: QK^T (3-term) + online softmax + PV -> fp16 att
    flash_attn<<<dim3(NH, SEQ / 128), blk, FA_SMEM>>>(qh, ql, kh, kl, vth, ath);

    // output projection (1-term, exact weights)
    gemm_o<<<dim3(DM / 128, SEQ / 128), blkG, O_SMEM>>>(ath, nibo, so, out);
}

// round 15
// speedup vs baseline: 1.1481x; 1.0321x over previous
#include <cuda_runtime.h>
#include <cuda_fp16.h>
#include <cstdint>
#include <cstring>

// ---------------------------------------------------------------------------
// Problem constants
// ---------------------------------------------------------------------------
#define SEQ   2048
#define DM    4096
#define NH    32
#define NKV   8
#define HD    128
#define KVD   (NKV * HD)   // 1024

typedef __half h16;

// ---------------------------------------------------------------------------
// Device-global scratch (allocation-free rule)
// ---------------------------------------------------------------------------
__device__ float g_xq[SEQ * DM];
__device__ float g_xk[SEQ * KVD];
__device__ float g_xv[SEQ * KVD];

__device__ __align__(16) h16 g_xh [SEQ * DM],  g_xl [SEQ * DM];  // x split
__device__ __align__(16) h16 g_qh [SEQ * DM],  g_ql [SEQ * DM];  // q split
__device__ __align__(16) h16 g_kh [SEQ * KVD], g_kl [SEQ * KVD]; // k split
__device__ __align__(16) h16 g_vth[NKV * HD * SEQ];              // V^T plain
__device__ __align__(16) h16 g_ath[SEQ * DM];                    // attention out

// exact fp16 nibble planes (weight = nib * group_scale)
__device__ __align__(16) h16 g_nibq[DM * DM];
__device__ __align__(16) h16 g_nibk[KVD * DM];
__device__ __align__(16) h16 g_nibv[KVD * DM];
__device__ __align__(16) h16 g_nibo[DM * DM];

__device__ int g_mode;

// ---------------------------------------------------------------------------
// PTX helpers (base sm_103 ISA: cp.async / ldmatrix / mma.sync)
// ---------------------------------------------------------------------------
__device__ __forceinline__ uint32_t smem_u32(const void* p) {
    uint32_t a;
    asm("{ .reg .u64 t; cvta.to.shared.u64 t, %1; cvt.u32.u64 %0, t; }" : "=r"(a) : "l"(p));
    return a;
}
__device__ __forceinline__ void cp16(uint32_t dst, const void* src) {
    asm volatile("cp.async.cg.shared.global [%0], [%1], 16;" :: "r"(dst), "l"(src) : "memory");
}
__device__ __forceinline__ void cp4(uint32_t dst, const void* src) {
    asm volatile("cp.async.ca.shared.global [%0], [%1], 4;" :: "r"(dst), "l"(src) : "memory");
}
__device__ __forceinline__ void cp_commit() {
    asm volatile("cp.async.commit_group;" ::: "memory");
}
template <int N>
__device__ __forceinline__ void cp_wait() {
    asm volatile("cp.async.wait_group %0;" :: "n"(N) : "memory");
}
__device__ __forceinline__ void ldm_x4(uint32_t* r, uint32_t addr) {
    asm volatile("ldmatrix.sync.aligned.m8n8.x4.shared.b16 {%0,%1,%2,%3}, [%4];"
                 : "=r"(r[0]), "=r"(r[1]), "=r"(r[2]), "=r"(r[3]) : "r"(addr));
}
__device__ __forceinline__ void mma_f32(float* d, const uint32_t* a,
                                        uint32_t b0, uint32_t b1) {
    asm volatile(
        "mma.sync.aligned.m16n8k16.row.col.f32.f16.f16.f32 "
        "{%0,%1,%2,%3}, {%4,%5,%6,%7}, {%8,%9}, {%0,%1,%2,%3};"
        : "+f"(d[0]), "+f"(d[1]), "+f"(d[2]), "+f"(d[3])
        : "r"(a[0]), "r"(a[1]), "r"(a[2]), "r"(a[3]), "r"(b0), "r"(b1));
}
__device__ __forceinline__ void mma_f16(uint32_t* d, const uint32_t* a,
                                        uint32_t b0, uint32_t b1) {
    asm volatile(
        "mma.sync.aligned.m16n8k16.row.col.f16.f16.f16.f16 "
        "{%0,%1}, {%2,%3,%4,%5}, {%6,%7}, {%0,%1};"
        : "+r"(d[0]), "+r"(d[1])
        : "r"(a[0]), "r"(a[1]), "r"(a[2]), "r"(a[3]), "r"(b0), "r"(b1));
}

// Pack two floats into one uint32 holding an fp16 pair (BOTH halves).
__device__ __forceinline__ uint32_t pack_h2(float a, float b) {
    __half2 t = __floats2half2_rn(a, b);
    uint32_t r;
    memcpy(&r, &t, 4);
    return r;
}

// Permuted conflict-free smem layouts: atom = 8 rows x 16B, 128B blocks.
__device__ __forceinline__ uint32_t off8(int row, int kc) {   // 64-wide fp16 tile
    return (uint32_t)((((row >> 3) * 8 + kc) << 7) + ((row & 7) << 4));
}
__device__ __forceinline__ uint32_t off16(int row, int kc) {  // 128-wide fp16 tile
    return (uint32_t)((((row >> 3) * 16 + kc) << 7) + ((row & 7) << 4));
}

// ---------------------------------------------------------------------------
// Probe (dtype-robust weight ingestion)
// ---------------------------------------------------------------------------
__global__ void probe_mode(const int* __restrict__ w)
{
    if (threadIdx.x == 0 && blockIdx.x == 0) {
        int ok = 0;
        for (int i = 0; i < 256; i++) {
            const int v = w[i];
            if (v >= -128 && v <= 127) ok++;
        }
        g_mode = (ok >= 250) ? 1 : 0;
    }
}

// Unpack Q4_0 nibbles directly from raw input (mode-aware) to fp16 planes.
__global__ __launch_bounds__(256) void unpack_nib_h(
    const void* __restrict__ in, h16* __restrict__ nib, long n)
{
    const int mode = g_mode;
    const long stride = (long)gridDim.x * blockDim.x;
    for (long f = (long)blockIdx.x * blockDim.x + threadIdx.x; f < n; f += stride) {
        const int  q = (int)(f & 127);
        const long b = (f >> 7) * 64 + (q & 63);
        const int8_t raw = mode ? (int8_t)((const int*)in)[b]
                                : ((const int8_t*)in)[b];
        const int v = (q < 64) ? (raw >> 4) : (((int8_t)(raw << 4)) >> 4);
        nib[f] = __float2half((float)v);
    }
}

// fp32 -> fp16 hi/lo split
__global__ __launch_bounds__(256) void split_f32(
    const float* __restrict__ src, h16* __restrict__ hi, h16* __restrict__ lo, long n)
{
    const long stride = (long)gridDim.x * blockDim.x;
    for (long i = (long)blockIdx.x * blockDim.x + threadIdx.x; i < n; i += stride) {
        const float v = src[i];
        const h16 h = __float2half(v);
        hi[i] = h;
        lo[i] = __float2half(v - __half2float(h));
    }
}

// ---------------------------------------------------------------------------
// RoPE (rotate-half) + optional scale + fp16 split.  x laid out [S, nh, HD].
// ---------------------------------------------------------------------------
__global__ __launch_bounds__(256) void rope_split(
    const float* __restrict__ x, const float* __restrict__ cosb,
    const float* __restrict__ sinb, h16* __restrict__ oh, h16* __restrict__ ol,
    int nheads, float scale)
{
    const long total = (long)SEQ * nheads * 64;
    long idx = (long)blockIdx.x * blockDim.x + threadIdx.x;
    if (idx >= total) return;
    const int d = (int)(idx & 63);
    const int h = (int)((idx >> 6) % nheads);
    const int s = (int)(idx / ((long)64 * nheads));
    const size_t base = (size_t)s * nheads * HD + h * HD + d;
    const float c  = cosb[s * 64 + d];
    const float sn = sinb[s * 64 + d];
    const float lo = x[base];
    const float hi = x[base + 64];
    const float r0 = (lo * c - hi * sn) * scale;
    const float r1 = (hi * c + lo * sn) * scale;
    h16 h0 = __float2half(r0);
    h16 h1 = __float2half(r1);
    oh[base]      = h0;
    ol[base]      = __float2half(r0 - __half2float(h0));
    oh[base + 64] = h1;
    ol[base + 64] = __float2half(r1 - __half2float(h1));
}

// ---------------------------------------------------------------------------
// Transpose V to plain fp16: vt[kv][d][s] = xv[s][kv*HD + d]
// ---------------------------------------------------------------------------
__global__ __launch_bounds__(256) void vtrans_h(
    const float* __restrict__ xv, h16* __restrict__ vt)
{
    const long total = (long)NKV * HD * SEQ;
    long idx = (long)blockIdx.x * blockDim.x + threadIdx.x;
    if (idx >= total) return;
    const int s  = (int)(idx % SEQ);
    const int d  = (int)((idx / SEQ) % HD);
    const int kv = (int)(idx / ((long)SEQ * HD));
    vt[idx] = __float2half(xv[(size_t)s * KVD + kv * HD + d]);
}

// ---------------------------------------------------------------------------
// Merged QKV projection GEMM at full 128x128 CTA tiles.
// 512 threads, 16 warps 4x4, warp tile 32x32, BK=64, 3-stage cp.async.
// 1-D grid, 768 CTAs: [0,512) q (2-term), [512,640) k (2-term),
// [640,768) v (1-term, light, scheduled last).
// ---------------------------------------------------------------------------
#define W4_TILE  16384                        // 128 x 64 fp16
#define W4_STAGE (3 * W4_TILE)                // Ah | Al | nib : 48 KB
#define W4_SMEM  (3 * W4_STAGE + 3 * 512)

__global__ __launch_bounds__(512, 1) void gemm_qkv(
    const h16* __restrict__ xh, const h16* __restrict__ xl,
    const h16* __restrict__ nq, const h16* __restrict__ nk,
    const h16* __restrict__ nv,
    const float* __restrict__ sq, const float* __restrict__ sk,
    const float* __restrict__ sv,
    float* __restrict__ xq, float* __restrict__ xk, float* __restrict__ xv)
{
    const int bx = blockIdx.x;
    const h16* Nib;
    const float* Sc;
    float* C;
    int ldc, n0, m0, two;
    if (bx < 512) {
        Nib = nq; Sc = sq; C = xq; ldc = DM; two = 1;
        n0 = (bx & 31) * 128; m0 = (bx >> 5) * 128;
    } else if (bx < 640) {
        const int i = bx - 512;
        Nib = nk; Sc = sk; C = xk; ldc = KVD; two = 1;
        n0 = (i & 7) * 128; m0 = (i >> 3) * 128;
    } else {
        const int i = bx - 640;
        Nib = nv; Sc = sv; C = xv; ldc = KVD; two = 0;
        n0 = (i & 7) * 128; m0 = (i >> 3) * 128;
    }

    extern __shared__ char smem[];
    const uint32_t sb  = smem_u32(smem);
    const uint32_t ssc = sb + 3 * W4_STAGE;
    const int tid  = threadIdx.x;
    const int wid  = tid >> 5;
    const int lane = tid & 31;

    const int NC = DM >> 6;
    const int KG = DM >> 6;

    const int wm = (wid & 3) * 32;
    const int wn = (wid >> 2) * 32;

    float accf[2][4][4];
#pragma unroll
    for (int i = 0; i < 2; i++)
#pragma unroll
        for (int j = 0; j < 4; j++)
#pragma unroll
            for (int v = 0; v < 4; v++) accf[i][j][v] = 0.0f;

    auto load_stage = [&](int c) {
        const int k0 = c << 6;
        const uint32_t st = sb + (uint32_t)(c % 3) * W4_STAGE;
        const int total = (two ? 3 : 2) << 10;
        for (int i = tid; i < total; i += 512) {
            const int tile = i >> 10;
            const int row  = (i >> 3) & 127;
            const int kc   = i & 7;
            const h16* src;
            uint32_t dstb;
            if (tile == 0)             { src = xh  + (size_t)(m0 + row) * DM + k0; dstb = st; }
            else if (two && tile == 1) { src = xl  + (size_t)(m0 + row) * DM + k0; dstb = st + W4_TILE; }
            else                       { src = Nib + (size_t)(n0 + row) * DM + k0; dstb = st + 2 * W4_TILE; }
            cp16(dstb + off8(row, kc), src + kc * 8);
        }
        if (tid < 128)
            cp4(ssc + (uint32_t)(c % 3) * 512 + tid * 4,
                Sc + (size_t)(n0 + tid) * KG + c);
        cp_commit();
    };

    load_stage(0);
    load_stage(1);

    const int lrow16 = lane & 15;
    const int lhi    = lane >> 4;

    for (int c = 0; c < NC; c++) {
        if (c + 1 < NC) cp_wait<1>();
        else            cp_wait<0>();
        __syncthreads();

        const uint32_t st = sb + (uint32_t)(c % 3) * W4_STAGE;
        const float* ss = (const float*)(smem + 3 * W4_STAGE + (c % 3) * 512);

        float accg[2][4][4];
#pragma unroll
        for (int i = 0; i < 2; i++)
#pragma unroll
            for (int j = 0; j < 4; j++)
#pragma unroll
                for (int v = 0; v < 4; v++) accg[i][j][v] = 0.0f;

#pragma unroll
        for (int kb = 0; kb < 4; kb++) {
            uint32_t afh[2][4], afl[2][4];
#pragma unroll
            for (int mt = 0; mt < 2; mt++) {
                const uint32_t off = off8(wm + mt * 16 + lrow16, kb * 2 + lhi);
                ldm_x4(afh[mt], st + off);
                if (two) ldm_x4(afl[mt], st + W4_TILE + off);
            }
#pragma unroll
            for (int g = 0; g < 2; g++) {
                uint32_t bf[4];
                ldm_x4(bf, st + 2 * W4_TILE + off8(wn + g * 16 + lrow16, kb * 2 + lhi));
#pragma unroll
                for (int mt = 0; mt < 2; mt++) {
#pragma unroll
                    for (int sub = 0; sub < 2; sub++) {
                        mma_f32(accg[mt][g * 2 + sub], afh[mt], bf[sub], bf[sub + 2]);
                        if (two)
                            mma_f32(accg[mt][g * 2 + sub], afl[mt], bf[sub], bf[sub + 2]);
                    }
                }
            }
        }

#pragma unroll
        for (int g = 0; g < 2; g++)
#pragma unroll
            for (int sub = 0; sub < 2; sub++) {
                const int nn = wn + g * 16 + sub * 8 + (lane & 3) * 2;
                const float s0 = ss[nn];
                const float s1 = ss[nn + 1];
#pragma unroll
                for (int mt = 0; mt < 2; mt++) {
                    float* f = accf[mt][g * 2 + sub];
                    const float* a = accg[mt][g * 2 + sub];
                    f[0] += a[0] * s0;
                    f[1] += a[1] * s1;
                    f[2] += a[2] * s0;
                    f[3] += a[3] * s1;
                }
            }

        if (c + 2 < NC) load_stage(c + 2);
    }

#pragma unroll
    for (int mt = 0; mt < 2; mt++) {
        const int mrow = m0 + wm + mt * 16 + (lane >> 2);
#pragma unroll
        for (int g = 0; g < 2; g++)
#pragma unroll
            for (int sub = 0; sub < 2; sub++) {
                const float* d = accf[mt][g * 2 + sub];
                const int n = n0 + wn + g * 16 + sub * 8 + (lane & 3) * 2;
                *(float2*)(C + (size_t)mrow * ldc + n)       = make_float2(d[0], d[1]);
                *(float2*)(C + (size_t)(mrow + 8) * ldc + n) = make_float2(d[2], d[3]);
            }
    }
}

// ---------------------------------------------------------------------------
// Output projection GEMM (1-term, exact nibble weights), wave-smoothed:
// CTA tile 128(M) x 64(N), 256 threads, 8 warps 4x2 (warp tile 32x32 —
// identical warp geometry & accumulation order to the 128x128 version),
// occupancy 2. 1024 CTAs -> per-SM work quantum halves -> no 4-wave rounding.
// ---------------------------------------------------------------------------
#define O_ATILE 16384                 // 128 x 64 fp16
#define O_BTILE 8192                  //  64 x 64 fp16
#define O_STAGE (O_ATILE + O_BTILE)   // 24 KB
#define O_SMEM  (3 * O_STAGE + 3 * 256)

__global__ __launch_bounds__(256, 2) void gemm_o(
    const h16* __restrict__ A, const h16* __restrict__ Nib,
    const float* __restrict__ Sc, float* __restrict__ C)
{
    const int m0 = blockIdx.y * 128;
    const int n0 = blockIdx.x * 64;

    extern __shared__ char smem[];
    const uint32_t sb  = smem_u32(smem);
    const uint32_t ssc = sb + 3 * O_STAGE;
    const int tid  = threadIdx.x;
    const int wid  = tid >> 5;
    const int lane = tid & 31;

    const int NC = DM >> 6;
    const int KG = DM >> 6;

    const int wm = (wid & 3) * 32;
    const int wn = (wid >> 2) * 32;     // 2 warp columns cover N=64

    float accf[2][4][4];
#pragma unroll
    for (int i = 0; i < 2; i++)
#pragma unroll
        for (int j = 0; j < 4; j++)
#pragma unroll
            for (int v = 0; v < 4; v++) accf[i][j][v] = 0.0f;

    auto load_stage = [&](int c) {
        const int k0 = c << 6;
        const uint32_t st = sb + (uint32_t)(c % 3) * O_STAGE;
        // A: 128 rows x 8 chunks = 1024 cp16; B: 64 rows x 8 = 512 cp16
        for (int i = tid; i < 1536; i += 256) {
            if (i < 1024) {
                const int row = i >> 3, kc = i & 7;
                cp16(st + off8(row, kc), A + (size_t)(m0 + row) * DM + k0 + kc * 8);
            } else {
                const int j = i - 1024;
                const int row = j >> 3, kc = j & 7;
                cp16(st + O_ATILE + off8(row, kc),
                     Nib + (size_t)(n0 + row) * DM + k0 + kc * 8);
            }
        }
        if (tid < 64)
            cp4(ssc + (uint32_t)(c % 3) * 256 + tid * 4,
                Sc + (size_t)(n0 + tid) * KG + c);
        cp_commit();
    };

    load_stage(0);
    load_stage(1);

    const int lrow16 = lane & 15;
    const int lhi    = lane >> 4;

    for (int c = 0; c < NC; c++) {
        if (c + 1 < NC) cp_wait<1>();
        else            cp_wait<0>();
        __syncthreads();

        const uint32_t st = sb + (uint32_t)(c % 3) * O_STAGE;
        const float* ss = (const float*)(smem + 3 * O_STAGE + (c % 3) * 256);

        float accg[2][4][4];
#pragma unroll
        for (int i = 0; i < 2; i++)
#pragma unroll
            for (int j = 0; j < 4; j++)
#pragma unroll
                for (int v = 0; v < 4; v++) accg[i][j][v] = 0.0f;

#pragma unroll
        for (int kb = 0; kb < 4; kb++) {
            uint32_t af[2][4];
#pragma unroll
            for (int mt = 0; mt < 2; mt++)
                ldm_x4(af[mt], st + off8(wm + mt * 16 + lrow16, kb * 2 + lhi));
#pragma unroll
            for (int g = 0; g < 2; g++) {
                uint32_t bf[4];
                ldm_x4(bf, st + O_ATILE + off8(wn + g * 16 + lrow16, kb * 2 + lhi));
#pragma unroll
                for (int mt = 0; mt < 2; mt++) {
#pragma unroll
                    for (int sub = 0; sub < 2; sub++)
                        mma_f32(accg[mt][g * 2 + sub], af[mt], bf[sub], bf[sub + 2]);
                }
            }
        }

#pragma unroll
        for (int g = 0; g < 2; g++)
#pragma unroll
            for (int sub = 0; sub < 2; sub++) {
                const int nn = wn + g * 16 + sub * 8 + (lane & 3) * 2;
                const float s0 = ss[nn];
                const float s1 = ss[nn + 1];
#pragma unroll
                for (int mt = 0; mt < 2; mt++) {
                    float* f = accf[mt][g * 2 + sub];
                    const float* a = accg[mt][g * 2 + sub];
                    f[0] += a[0] * s0;
                    f[1] += a[1] * s1;
                    f[2] += a[2] * s0;
                    f[3] += a[3] * s1;
                }
            }

        if (c + 2 < NC) load_stage(c + 2);
    }

#pragma unroll
    for (int mt = 0; mt < 2; mt++) {
        const int mrow = m0 + wm + mt * 16 + (lane >> 2);
#pragma unroll
        for (int g = 0; g < 2; g++)
#pragma unroll
            for (int sub = 0; sub < 2; sub++) {
                const float* d = accf[mt][g * 2 + sub];
                const int n = n0 + wn + g * 16 + sub * 8 + (lane & 3) * 2;
                *(float2*)(C + (size_t)mrow * DM + n)       = make_float2(d[0], d[1]);
                *(float2*)(C + (size_t)(mrow + 8) * DM + n) = make_float2(d[2], d[3]);
            }
    }
}

// ---------------------------------------------------------------------------
// Fused flash attention: S = Q K^T (3-term split) -> online softmax -> O = P V.
// Grid (NH, 16 q-tiles, heavy first). 256 threads, 8 warps; warp = 16 q-rows
// x full 128-key tile.  Diagonal tiles skip key groups above the causal edge.
// ---------------------------------------------------------------------------
#define FA_QH 0
#define FA_QL 32768
#define FA_KH 65536
#define FA_KL 98304
#define FA_V0 131072
#define FA_V1 163840
#define FA_SMEM 196608

__global__ __launch_bounds__(256, 1) void flash_attn(
    const h16* __restrict__ Qh, const h16* __restrict__ Ql,
    const h16* __restrict__ Kh, const h16* __restrict__ Kl,
    const h16* __restrict__ Vt, h16* __restrict__ O)
{
    extern __shared__ char smem[];
    const uint32_t sb = smem_u32(smem);
    const int h   = blockIdx.x;
    const int qt  = gridDim.y - 1 - blockIdx.y;   // heavy tiles first
    const int kvh = h / (NH / NKV);
    const int tid = threadIdx.x;
    const int wid = tid >> 5;
    const int lane = tid & 31;
    const int NT = qt + 1;

    for (int i = tid; i < 2048; i += 256) {
        const int row = i >> 4, c = i & 15;
        const size_t g = (size_t)(qt * 128 + row) * DM + h * HD + c * 8;
        cp16(sb + FA_QH + off16(row, c), Qh + g);
        cp16(sb + FA_QL + off16(row, c), Ql + g);
    }
    cp_commit();
    for (int i = tid; i < 2048; i += 256) {
        const int row = i >> 4, c = i & 15;
        const size_t g = (size_t)row * KVD + kvh * HD + c * 8;
        cp16(sb + FA_KH + off16(row, c), Kh + g);
        cp16(sb + FA_KL + off16(row, c), Kl + g);
    }
    cp_commit();
    for (int i = tid; i < 2048; i += 256) {
        const int row = i >> 4, c = i & 15;
        cp16(sb + FA_V0 + off16(row, c), Vt + (size_t)(kvh * HD + row) * SEQ + c * 8);
    }
    cp_commit();
    cp_wait<1>();
    __syncthreads();

    const int g8     = lane >> 2;
    const int qd     = lane & 3;
    const int lrow16 = lane & 15;
    const int lhi    = lane >> 4;
    const int wq     = wid * 16;

    float of[16][4];
#pragma unroll
    for (int j = 0; j < 16; j++)
#pragma unroll
        for (int v = 0; v < 4; v++) of[j][v] = 0.0f;
    float m0 = -1e30f, m1 = -1e30f, l0 = 0.0f, l1 = 0.0f;

    for (int kt = 0; kt < NT; kt++) {
        const int gmax = (kt == qt) ? (wid + 1) : 8;   // causal key-group bound

        float    accf[16][4];
        uint32_t accc[16][2];
#pragma unroll
        for (int j = 0; j < 16; j++) {
#pragma unroll
            for (int v = 0; v < 4; v++) accf[j][v] = 0.0f;
            accc[j][0] = 0u; accc[j][1] = 0u;
        }

#pragma unroll
        for (int kb = 0; kb < 8; kb++) {
            uint32_t aqh[4], aql[4];
            const uint32_t aoff = off16(wq + lrow16, kb * 2 + lhi);
            ldm_x4(aqh, sb + FA_QH + aoff);
            ldm_x4(aql, sb + FA_QL + aoff);
#pragma unroll
            for (int g = 0; g < 8; g++) {
                if (g >= gmax) break;
                const uint32_t boff = off16(g * 16 + lrow16, kb * 2 + lhi);
                uint32_t bkh[4], bkl[4];
                ldm_x4(bkh, sb + FA_KH + boff);
                ldm_x4(bkl, sb + FA_KL + boff);
#pragma unroll
                for (int sub = 0; sub < 2; sub++) {
                    mma_f32(accf[g * 2 + sub], aqh, bkh[sub], bkh[sub + 2]);
                    mma_f16(accc[g * 2 + sub], aqh, bkl[sub], bkl[sub + 2]);
                    mma_f16(accc[g * 2 + sub], aql, bkh[sub], bkh[sub + 2]);
                }
            }
        }
#pragma unroll
        for (int j = 0; j < 16; j++) {
            const __half2 c0 = *(const __half2*)&accc[j][0];
            const __half2 c1 = *(const __half2*)&accc[j][1];
            accf[j][0] += __low2float(c0);
            accf[j][1] += __high2float(c0);
            accf[j][2] += __low2float(c1);
            accf[j][3] += __high2float(c1);
        }
        if (kt == qt) {
            const int r0 = wq + g8, r1 = r0 + 8;
#pragma unroll
            for (int j = 0; j < 16; j++) {
                const int cb = j * 8 + qd * 2;
                if (cb     > r0) accf[j][0] = -1e30f;
                if (cb + 1 > r0) accf[j][1] = -1e30f;
                if (cb     > r1) accf[j][2] = -1e30f;
                if (cb + 1 > r1) accf[j][3] = -1e30f;
            }
        }
        // ---- online softmax ----
        float mx0 = -1e30f, mx1 = -1e30f;
#pragma unroll
        for (int j = 0; j < 16; j++) {
            mx0 = fmaxf(mx0, fmaxf(accf[j][0], accf[j][1]));
            mx1 = fmaxf(mx1, fmaxf(accf[j][2], accf[j][3]));
        }
        mx0 = fmaxf(mx0, __shfl_xor_sync(0xffffffffu, mx0, 1));
        mx0 = fmaxf(mx0, __shfl_xor_sync(0xffffffffu, mx0, 2));
        mx1 = fmaxf(mx1, __shfl_xor_sync(0xffffffffu, mx1, 1));
        mx1 = fmaxf(mx1, __shfl_xor_sync(0xffffffffu, mx1, 2));

        const float nm0 = fmaxf(m0, mx0);
        const float nm1 = fmaxf(m1, mx1);
        const float sc0 = __expf(m0 - nm0);
        const float sc1 = __expf(m1 - nm1);
        float sum0 = 0.0f, sum1 = 0.0f;
#pragma unroll
        for (int j = 0; j < 16; j++) {
            accf[j][0] = __expf(accf[j][0] - nm0);
            accf[j][1] = __expf(accf[j][1] - nm0);
            accf[j][2] = __expf(accf[j][2] - nm1);
            accf[j][3] = __expf(accf[j][3] - nm1);
            sum0 += accf[j][0] + accf[j][1];
            sum1 += accf[j][2] + accf[j][3];
        }
        sum0 += __shfl_xor_sync(0xffffffffu, sum0, 1);
        sum0 += __shfl_xor_sync(0xffffffffu, sum0, 2);
        sum1 += __shfl_xor_sync(0xffffffffu, sum1, 1);
        sum1 += __shfl_xor_sync(0xffffffffu, sum1, 2);
        l0 = l0 * sc0 + sum0;
        l1 = l1 * sc1 + sum1;
        m0 = nm0;
        m1 = nm1;
#pragma unroll
        for (int j = 0; j < 16; j++) {
            of[j][0] *= sc0; of[j][1] *= sc0;
            of[j][2] *= sc1; of[j][3] *= sc1;
        }

        __syncthreads();

        const uint32_t vb = (kt & 1) ? FA_V1 : FA_V0;
        if (kt + 1 < NT) {
            const int kt1 = kt + 1;
            for (int i = tid; i < 2048; i += 256) {
                const int row = i >> 4, c = i & 15;
                const size_t g = (size_t)(kt1 * 128 + row) * KVD + kvh * HD + c * 8;
                cp16(sb + FA_KH + off16(row, c), Kh + g);
                cp16(sb + FA_KL + off16(row, c), Kl + g);
            }
            cp_commit();
            const uint32_t vb1 = (kt1 & 1) ? FA_V1 : FA_V0;
            for (int i = tid; i < 2048; i += 256) {
                const int row = i >> 4, c = i & 15;
                cp16(sb + vb1 + off16(row, c),
                     Vt + (size_t)(kvh * HD + row) * SEQ + kt1 * 128 + c * 8);
            }
            cp_commit();
            cp_wait<2>();
        } else {
            cp_wait<0>();
        }
        __syncthreads();

        // ---- O += P V (skip zero P chunks on diagonal) ----
#pragma unroll
        for (int c = 0; c < 8; c++) {
            if (c >= gmax) break;
            uint32_t pa[4];
            pa[0] = pack_h2(accf[2 * c][0],     accf[2 * c][1]);
            pa[1] = pack_h2(accf[2 * c][2],     accf[2 * c][3]);
            pa[2] = pack_h2(accf[2 * c + 1][0], accf[2 * c + 1][1]);
            pa[3] = pack_h2(accf[2 * c + 1][2], accf[2 * c + 1][3]);
#pragma unroll
            for (int gn = 0; gn < 8; gn++) {
                uint32_t bf[4];
                ldm_x4(bf, sb + vb + off16(gn * 16 + lrow16, c * 2 + lhi));
                mma_f32(of[gn * 2 + 0], pa, bf[0], bf[2]);
                mma_f32(of[gn * 2 + 1], pa, bf[1], bf[3]);
            }
        }

        if (kt + 1 < NT) { cp_wait<1>(); __syncthreads(); }
    }

    const float inv0 = 1.0f / l0;
    const float inv1 = 1.0f / l1;
    const int s0 = qt * 128 + wq + g8;
#pragma unroll
    for (int j = 0; j < 16; j++) {
        const int d = h * HD + j * 8 + qd * 2;
        *(__half2*)(O + (size_t)s0 * DM + d) =
            __floats2half2_rn(of[j][0] * inv0, of[j][1] * inv0);
        *(__half2*)(O + (size_t)(s0 + 8) * DM + d) =
            __floats2half2_rn(of[j][2] * inv1, of[j][3] * inv1);
    }
}

// ---------------------------------------------------------------------------
// Launch
// ---------------------------------------------------------------------------
extern "C" void kernel_launch(void* const* d_in, const int* in_sizes, int n_in,
                              void* d_out, int out_size)
{
    (void)in_sizes; (void)n_in; (void)out_size;
    const float* x    = (const float*)d_in[0];
    const void*  wq   = d_in[1];
    const float* sq   = (const float*)d_in[2];
    const void*  wk   = d_in[3];
    const float* sk   = (const float*)d_in[4];
    const void*  wv   = d_in[5];
    const float* sv   = (const float*)d_in[6];
    const void*  wo   = d_in[7];
    const float* so   = (const float*)d_in[8];
    const float* cosb = (const float*)d_in[9];
    const float* sinb = (const float*)d_in[10];
    float* out = (float*)d_out;

    float *xq, *xk, *xv;
    h16 *xh, *xl, *qh, *ql, *kh, *kl, *vth, *ath;
    h16 *nibq, *nibk, *nibv, *nibo;

    cudaGetSymbolAddress((void**)&xq,  g_xq);
    cudaGetSymbolAddress((void**)&xk,  g_xk);
    cudaGetSymbolAddress((void**)&xv,  g_xv);
    cudaGetSymbolAddress((void**)&xh,  g_xh);   cudaGetSymbolAddress((void**)&xl,  g_xl);
    cudaGetSymbolAddress((void**)&qh,  g_qh);   cudaGetSymbolAddress((void**)&ql,  g_ql);
    cudaGetSymbolAddress((void**)&kh,  g_kh);   cudaGetSymbolAddress((void**)&kl,  g_kl);
    cudaGetSymbolAddress((void**)&vth, g_vth);
    cudaGetSymbolAddress((void**)&ath, g_ath);
    cudaGetSymbolAddress((void**)&nibq, g_nibq); cudaGetSymbolAddress((void**)&nibk, g_nibk);
    cudaGetSymbolAddress((void**)&nibv, g_nibv); cudaGetSymbolAddress((void**)&nibo, g_nibo);

    cudaFuncSetAttribute(gemm_qkv,  cudaFuncAttributeMaxDynamicSharedMemorySize, W4_SMEM);
    cudaFuncSetAttribute(gemm_o,    cudaFuncAttributeMaxDynamicSharedMemorySize, O_SMEM);
    cudaFuncSetAttribute(flash_attn, cudaFuncAttributeMaxDynamicSharedMemorySize, FA_SMEM);

    const dim3 blk(256);
    const dim3 blkG(512);

    // ingest; launch #6 = gemm_qkv (ncu window)
    probe_mode<<<1, 32>>>((const int*)wq);                                 // 1
    unpack_nib_h<<<2048, blk>>>(wq, nibq, (long)DM * DM);                  // 2
    split_f32<<<2048, blk>>>(x, xh, xl, (long)SEQ * DM);                   // 3
    unpack_nib_h<<<2048, blk>>>(wk, nibk, (long)KVD * DM);                 // 4
    unpack_nib_h<<<2048, blk>>>(wv, nibv, (long)KVD * DM);                 // 5
    gemm_qkv<<<768, blkG, W4_SMEM>>>(                                      // 6 (ncu)
        xh, xl, nibq, nibk, nibv, sq, sk, sv, xq, xk, xv);

    unpack_nib_h<<<2048, blk>>>(wo, nibo, (long)DM * DM);

    rope_split<<<(SEQ * NH  * 64 + 255) / 256, blk>>>(xq, cosb, sinb, qh, ql, NH,
                                                      0.08838834764831843f);
    rope_split<<<(SEQ * NKV * 64 + 255) / 256, blk>>>(xk, cosb, sinb, kh, kl, NKV, 1.0f);
    vtrans_h<<<(NKV * HD * SEQ + 255) / 256, blk>>>(xv, vth);

    // fused attention: QK^T (3-term) + online softmax + PV -> fp16 att
    flash_attn<<<dim3(NH, SEQ / 128), blk, FA_SMEM>>>(qh, ql, kh, kl, vth, ath);

    // output projection (1-term, exact weights, wave-smoothed tiles)
    gemm_o<<<dim3(DM / 64, SEQ / 128), blk, O_SMEM>>>(ath, nibo, so, out);
}